// round 9
// baseline (speedup 1.0000x reference)
#include <cuda_runtime.h>
#include <cuda_bf16.h>
#include <stdint.h>

// TargetEncoder: out[b, v] = f32( bf16( max over t with ids[b,t]==v of w[b,t], 0 baseline ) )
// ids: (1024,256) int32; w: (1024,256) f32; out: (1024,30522) f32. 125 MB write-bound.
//
// R8 passed (23.04us, rel_err 0) with full-row CTAs; profile showed nothing
// saturated (DRAM 38%, issue 21%) => latency/overlap bound. This version:
//  - 2048 half-row CTAs x 256 threads, 30.5 KB smem -> ~7 CTA/SM, ~2.0 waves
//  - prefetch the CTA's 256 (id, w) pairs into registers BEFORE the smem zero
//    loop so the ~700cyc LDG latency hides under the zeroing
//  - 16-bit CAS scatter-max on bf16 bits (order-isomorphic for non-negatives;
//    RN rounding monotone => bit-exact), streaming float2 writeout.

static constexpr int B_ROWS  = 1024;
static constexpr int V       = 30522;
static constexpr int SPLIT   = 15264;          // half0 [0,15264), half1 [15264,30522)
static constexpr int LEN1    = V - SPLIT;      // 15258 (even; base 16B-aligned)
static constexpr int S       = 256;
static constexpr int THREADS = 256;

__global__ __launch_bounds__(THREADS) void target_encoder_kernel(
    const int*   __restrict__ ids,   // (B, S) int32
    const float* __restrict__ w,     // (B, S) float32
    float*       __restrict__ out)   // (B, V) float32
{
    extern __shared__ unsigned short srow[];   // SPLIT entries (30528 B)
    const int cta  = blockIdx.x;
    const int b    = cta >> 1;
    const int half = cta & 1;
    const int vbase = half ? SPLIT : 0;
    const int len   = half ? LEN1  : SPLIT;
    const int tid  = threadIdx.x;

    // --- 0. prefetch this row's token (one per thread; THREADS == S) ---
    const int   my_v = ids[b * S + tid];
    const float my_w = w  [b * S + tid];

    // --- 1. zero the half-row in SMEM (uint4 = 8 bf16) ---
    uint4* s4 = reinterpret_cast<uint4*>(srow);
    #pragma unroll
    for (int i = tid; i < SPLIT / 8; i += THREADS) {   // 954 uint4s, 4 iters
        s4[i] = make_uint4(0u, 0u, 0u, 0u);
    }
    __syncthreads();

    // --- 2. scatter-max tokens belonging to this half (16-bit CAS) ---
    {
        const int rv = my_v - vbase;
        if ((unsigned)rv < (unsigned)len) {
            const unsigned short bits = __bfloat16_as_ushort(__float2bfloat16(my_w));
            unsigned short old = srow[rv];
            while (bits > old) {
                unsigned short prev = atomicCAS(&srow[rv], old, bits);
                if (prev == old) break;
                old = prev;
            }
        }
    }
    __syncthreads();

    // --- 3. streaming write-out, bf16 -> f32 exact upcast, float2 stores ---
    const unsigned int* su = reinterpret_cast<const unsigned int*>(srow);
    float2* dst = reinterpret_cast<float2*>(out + (size_t)b * V + vbase);
    const int n2 = len / 2;                    // 7632 or 7629 float2s
    #pragma unroll 4
    for (int i = tid; i < n2; i += THREADS) {
        const unsigned int pk = su[i];
        float2 o;
        o.x = __uint_as_float((pk & 0xFFFFu) << 16);
        o.y = __uint_as_float((pk >> 16)     << 16);
        __stcs(dst + i, o);
    }
}

extern "C" void kernel_launch(void* const* d_in, const int* in_sizes, int n_in,
                              void* d_out, int out_size)
{
    const int*   ids = (const int*)  d_in[0];
    const float* wts = (const float*)d_in[1];
    float*       out = (float*)      d_out;

    const size_t smem = SPLIT * sizeof(unsigned short);   // 30528 B
    cudaFuncSetAttribute(target_encoder_kernel,
                         cudaFuncAttributeMaxDynamicSharedMemorySize, (int)smem);

    target_encoder_kernel<<<2 * B_ROWS, THREADS, smem>>>(ids, wts, out);
}